// round 1
// baseline (speedup 1.0000x reference)
#include <cuda_runtime.h>
#include <math.h>
#include <stdint.h>

#define NB   4096
#define NN   524288
#define HDIM 128
#define HID  64

// scratch (static device memory — allowed)
__device__ float g_scores[NN];
__device__ int   g_off[NB + 1];

__device__ __forceinline__ float fast_tanh(float x) {
    // tanh(x) = 1 - 2/(exp(2x)+1); saturates correctly at +-inf
    float e = __expf(2.0f * x);
    return 1.0f - __fdividef(2.0f, e + 1.0f);
}
__device__ __forceinline__ float wmax(float v) {
#pragma unroll
    for (int o = 16; o; o >>= 1) v = fmaxf(v, __shfl_xor_sync(0xffffffffu, v, o));
    return v;
}
__device__ __forceinline__ float wsum(float v) {
#pragma unroll
    for (int o = 16; o; o >>= 1) v += __shfl_xor_sync(0xffffffffu, v, o);
    return v;
}

// ---------------------------------------------------------------------------
// Kernel 1: segment offsets. ball_batch is sorted; off[b] = lower_bound(batch, b)
// ---------------------------------------------------------------------------
__global__ void offsets_kernel(const int* __restrict__ batch) {
    int b = blockIdx.x * blockDim.x + threadIdx.x;
    if (b > NB) return;
    int lo = 0, hi = NN;
    while (lo < hi) {
        int mid = (lo + hi) >> 1;
        if (batch[mid] < b) lo = mid + 1; else hi = mid;
    }
    g_off[b] = lo;
}

// ---------------------------------------------------------------------------
// Kernel 2: attention scores = tanh(ball @ W1 + b1) @ w2 + b2     -> g_scores[N]
// Register-tiled GEMM, 128 nodes per block, f32x2 packed FMA.
// ---------------------------------------------------------------------------
#define AS_LD 129
#define SM_W1 (128 * AS_LD)          // 16512 floats
#define SM_W2 (SM_W1 + 128 * 64)     // 24704
#define SM_B1 (SM_W2 + 64)           // 24768
#define SM_TOT (SM_B1 + 64)          // 24832 floats = 99328 bytes

__global__ __launch_bounds__(128) void scores_kernel(
    const float* __restrict__ ball, const float* __restrict__ w1,
    const float* __restrict__ b1, const float* __restrict__ w2,
    const float* __restrict__ b2)
{
    extern __shared__ float sm[];
    float* As  = sm;
    float* W1s = sm + SM_W1;
    float* w2s = sm + SM_W2;
    float* b1s = sm + SM_B1;
    int t = threadIdx.x;

    // load 128x128 A tile (pad 129 for conflict-free column reads)
    const float* Ablk = ball + (size_t)blockIdx.x * 128 * HDIM;
#pragma unroll
    for (int it = 0; it < 32; it++) {
        int f4 = t + 128 * it;           // 4096 float4 total
        int row = f4 >> 5;
        int c = (f4 & 31) << 2;
        float4 v = ((const float4*)Ablk)[f4];
        float* d = &As[row * AS_LD + c];
        d[0] = v.x; d[1] = v.y; d[2] = v.z; d[3] = v.w;
    }
#pragma unroll
    for (int it = 0; it < 16; it++) {
        int f4 = t + 128 * it;           // 2048 float4 = full W1 (128x64)
        ((float4*)W1s)[f4] = ((const float4*)w1)[f4];
    }
    if (t < 64) { w2s[t] = w2[t]; b1s[t] = b1[t]; }
    __syncthreads();

    // thread tile: 8 rows (stride 16) x 8 hidden cols (contiguous pairs)
    int tm = t & 15, tn = t >> 4;
    uint64_t acc[8][4];
    {
        const ulonglong2* bi = (const ulonglong2*)&b1s[tn * 8];
        ulonglong2 p0 = bi[0], p1 = bi[1];
        uint64_t init0 = p0.x, init1 = p0.y, init2 = p1.x, init3 = p1.y;
#pragma unroll
        for (int r = 0; r < 8; r++) {
            acc[r][0] = init0; acc[r][1] = init1;
            acc[r][2] = init2; acc[r][3] = init3;
        }
    }
#pragma unroll 2
    for (int k = 0; k < 128; k++) {
        const ulonglong2* bp = (const ulonglong2*)&W1s[k * 64 + tn * 8];
        ulonglong2 q0 = bp[0], q1 = bp[1];
        uint64_t bb0 = q0.x, bb1 = q0.y, bb2 = q1.x, bb3 = q1.y;
#pragma unroll
        for (int r = 0; r < 8; r++) {
            float a = As[(tm + 16 * r) * AS_LD + k];
            uint64_t a2;
            asm("mov.b64 %0, {%1, %1};" : "=l"(a2) : "f"(a));
            asm("fma.rn.f32x2 %0, %1, %2, %0;" : "+l"(acc[r][0]) : "l"(a2), "l"(bb0));
            asm("fma.rn.f32x2 %0, %1, %2, %0;" : "+l"(acc[r][1]) : "l"(a2), "l"(bb1));
            asm("fma.rn.f32x2 %0, %1, %2, %0;" : "+l"(acc[r][2]) : "l"(a2), "l"(bb2));
            asm("fma.rn.f32x2 %0, %1, %2, %0;" : "+l"(acc[r][3]) : "l"(a2), "l"(bb3));
        }
    }

    // epilogue: tanh + dot with w2, reduce across the 8 tn groups
    float w2v[8];
#pragma unroll
    for (int c = 0; c < 8; c++) w2v[c] = w2s[tn * 8 + c];
    float part[8];
#pragma unroll
    for (int r = 0; r < 8; r++) {
        float p = 0.f;
#pragma unroll
        for (int i = 0; i < 4; i++) {
            float lo, hi;
            asm("mov.b64 {%0, %1}, %2;" : "=f"(lo), "=f"(hi) : "l"(acc[r][i]));
            p += fast_tanh(lo) * w2v[2 * i] + fast_tanh(hi) * w2v[2 * i + 1];
        }
        part[r] = p;
    }
    __syncthreads();
    float* red = As;  // reuse A tile smem: red[tn][m]
#pragma unroll
    for (int r = 0; r < 8; r++) red[tn * 128 + tm + 16 * r] = part[r];
    __syncthreads();
    float s = b2[0];
#pragma unroll
    for (int q = 0; q < 8; q++) s += red[q * 128 + t];
    g_scores[(size_t)blockIdx.x * 128 + t] = s;
}

// ---------------------------------------------------------------------------
// Kernel 3: per-graph segment softmax + weighted pooling + combiner + LN
//           + GELU + boundary/wicket heads. One block (128 threads) per graph.
// ---------------------------------------------------------------------------
#define CHUNK 1024

__global__ __launch_bounds__(128) void pool_combine_kernel(
    const float* __restrict__ ball, const float* __restrict__ query,
    const float* __restrict__ comb_w, const float* __restrict__ comb_b,
    const float* __restrict__ ln_g, const float* __restrict__ ln_b,
    const float* __restrict__ bnd_w1, const float* __restrict__ bnd_b1,
    const float* __restrict__ bnd_w2, const float* __restrict__ bnd_b2,
    const float* __restrict__ wkt_w1, const float* __restrict__ wkt_b1,
    const float* __restrict__ wkt_w2, const float* __restrict__ wkt_b2,
    float* __restrict__ out)
{
    __shared__ float wbuf[CHUNK];
    __shared__ float xbuf[256];
    __shared__ float hbuf[128];
    __shared__ float rsm[4];

    int b = blockIdx.x;
    int t = threadIdx.x;
    int warp = t >> 5, lane = t & 31;
    int start = g_off[b], end = g_off[b + 1];

    // segment max
    float mx = -3.4e38f;
    for (int i = start + t; i < end; i += 128) mx = fmaxf(mx, g_scores[i]);
    mx = wmax(mx);
    if (lane == 0) rsm[warp] = mx;
    __syncthreads();
    mx = fmaxf(fmaxf(rsm[0], rsm[1]), fmaxf(rsm[2], rsm[3]));
    __syncthreads();

    // segment sum of exp
    float se = 0.f;
    for (int i = start + t; i < end; i += 128) se += __expf(g_scores[i] - mx);
    se = wsum(se);
    if (lane == 0) rsm[warp] = se;
    __syncthreads();
    se = rsm[0] + rsm[1] + rsm[2] + rsm[3];
    float inv = (end > start) ? 1.0f / se : 0.0f;
    __syncthreads();

    // weighted pooling: thread t owns feature column t
    float pooled = 0.f;
    for (int cs = start; cs < end; cs += CHUNK) {
        int ce = min(end, cs + CHUNK);
        for (int i = cs + t; i < ce; i += 128)
            wbuf[i - cs] = __expf(g_scores[i] - mx) * inv;
        __syncthreads();
        const float* bp = ball + (size_t)cs * HDIM + t;
        int n = ce - cs;
        float a0 = 0.f, a1 = 0.f, a2 = 0.f, a3 = 0.f;
        int i = 0;
        for (; i + 8 <= n; i += 8) {
            a0 += wbuf[i]     * bp[(size_t)(i)     * HDIM];
            a1 += wbuf[i + 1] * bp[(size_t)(i + 1) * HDIM];
            a2 += wbuf[i + 2] * bp[(size_t)(i + 2) * HDIM];
            a3 += wbuf[i + 3] * bp[(size_t)(i + 3) * HDIM];
            a0 += wbuf[i + 4] * bp[(size_t)(i + 4) * HDIM];
            a1 += wbuf[i + 5] * bp[(size_t)(i + 5) * HDIM];
            a2 += wbuf[i + 6] * bp[(size_t)(i + 6) * HDIM];
            a3 += wbuf[i + 7] * bp[(size_t)(i + 7) * HDIM];
        }
        for (; i < n; i++) a0 += wbuf[i] * bp[(size_t)i * HDIM];
        pooled += (a0 + a1) + (a2 + a3);
        __syncthreads();
    }

    // combiner: h = [query | pooled] @ comb_w + comb_b
    xbuf[t] = query[(size_t)b * HDIM + t];
    xbuf[128 + t] = pooled;
    __syncthreads();
    float h0 = comb_b[t], h1 = 0.f, h2 = 0.f, h3 = 0.f;
#pragma unroll 4
    for (int k = 0; k < 256; k += 4) {
        h0 += xbuf[k]     * comb_w[(k)     * HDIM + t];
        h1 += xbuf[k + 1] * comb_w[(k + 1) * HDIM + t];
        h2 += xbuf[k + 2] * comb_w[(k + 2) * HDIM + t];
        h3 += xbuf[k + 3] * comb_w[(k + 3) * HDIM + t];
    }
    float hv = (h0 + h1) + (h2 + h3);

    // LayerNorm
    float s1 = wsum(hv);
    __syncthreads();
    if (lane == 0) rsm[warp] = s1;
    __syncthreads();
    float mu = (rsm[0] + rsm[1] + rsm[2] + rsm[3]) * (1.0f / 128.0f);
    float d = hv - mu;
    float s2 = wsum(d * d);
    __syncthreads();
    if (lane == 0) rsm[warp] = s2;
    __syncthreads();
    float var = (rsm[0] + rsm[1] + rsm[2] + rsm[3]) * (1.0f / 128.0f);
    hv = (d / sqrtf(var + 1e-5f)) * ln_g[t] + ln_b[t];
    // exact GELU
    hv = 0.5f * hv * (1.0f + erff(hv * 0.70710678118654752f));
    hbuf[t] = hv;
    __syncthreads();

    // heads: warps 0-1 -> boundary, warps 2-3 -> wicket
    const float* hw1 = (t < 64) ? bnd_w1 : wkt_w1;
    const float* hb1 = (t < 64) ? bnd_b1 : wkt_b1;
    const float* hw2 = (t < 64) ? bnd_w2 : wkt_w2;
    int j = t & 63;
    float c0 = hb1[j], c1 = 0.f, c2 = 0.f, c3 = 0.f;
#pragma unroll 4
    for (int k = 0; k < 128; k += 4) {
        c0 += hbuf[k]     * hw1[(k)     * 64 + j];
        c1 += hbuf[k + 1] * hw1[(k + 1) * 64 + j];
        c2 += hbuf[k + 2] * hw1[(k + 2) * 64 + j];
        c3 += hbuf[k + 3] * hw1[(k + 3) * 64 + j];
    }
    float hh = (c0 + c1) + (c2 + c3);
    hh = fmaxf(hh, 0.f) * hw2[j];
    float ws = wsum(hh);
    __syncthreads();
    if (lane == 0) rsm[warp] = ws;
    __syncthreads();
    if (t == 0) out[b]      = rsm[0] + rsm[1] + bnd_b2[0];
    if (t == 1) out[NB + b] = rsm[2] + rsm[3] + wkt_b2[0];
}

// ---------------------------------------------------------------------------
extern "C" void kernel_launch(void* const* d_in, const int* in_sizes, int n_in,
                              void* d_out, int out_size) {
    const float* query = (const float*)d_in[0];
    const float* ball  = (const float*)d_in[1];
    const int*   batch = (const int*)d_in[2];
    const float* aw1 = (const float*)d_in[3];
    const float* ab1 = (const float*)d_in[4];
    const float* aw2 = (const float*)d_in[5];
    const float* ab2 = (const float*)d_in[6];
    const float* cw  = (const float*)d_in[7];
    const float* cb  = (const float*)d_in[8];
    const float* lg  = (const float*)d_in[9];
    const float* lb  = (const float*)d_in[10];
    const float* bw1 = (const float*)d_in[11];
    const float* bb1 = (const float*)d_in[12];
    const float* bw2 = (const float*)d_in[13];
    const float* bb2 = (const float*)d_in[14];
    const float* ww1 = (const float*)d_in[15];
    const float* wb1 = (const float*)d_in[16];
    const float* ww2 = (const float*)d_in[17];
    const float* wb2 = (const float*)d_in[18];
    float* out = (float*)d_out;

    constexpr int smem_bytes = SM_TOT * (int)sizeof(float);  // 99328
    cudaFuncSetAttribute(scores_kernel,
                         cudaFuncAttributeMaxDynamicSharedMemorySize, smem_bytes);

    offsets_kernel<<<(NB + 1 + 255) / 256, 256>>>(batch);
    scores_kernel<<<NN / 128, 128, smem_bytes>>>(ball, aw1, ab1, aw2, ab2);
    pool_combine_kernel<<<NB, 128>>>(ball, query, cw, cb, lg, lb,
                                     bw1, bb1, bw2, bb2,
                                     ww1, wb1, ww2, wb2, out);
}